// round 6
// baseline (speedup 1.0000x reference)
#include <cuda_runtime.h>
#include <cstdint>
#include <math.h>

#define BB 8
#define DD 1024
#define HH 16
#define HD 64
#define PAST 8192
#define NSPLIT 8
#define CHUNK (PAST / NSPLIT)   // 1024 keys per block

// ---------------- scratch (no allocations allowed) ----------------
__device__ float g_qkv[3 * BB * DD];               // [m][b][d] raw (pre-RoPE) q,k,v
__device__ float g_part_o[BB * HH * NSPLIT * HD];  // sum p*v per split
__device__ float g_part_l[BB * HH * NSPLIT];       // sum p per split
__device__ float g_attn[BB * DD];                  // attention output before Wo
__device__ float g_cos[HD / 2];
__device__ float g_sin[HD / 2];
__device__ int   g_cnt[BB * HH];                   // zero-init; self-resetting

// ---------------- helpers ----------------
__device__ __forceinline__ void cp_async16(uint32_t saddr, const void* gaddr) {
    asm volatile("cp.async.cg.shared.global [%0], [%1], 16;" :: "r"(saddr), "l"(gaddr));
}

__device__ __forceinline__ void load_row(float4 dst[8],
                                         const float* __restrict__ Wq,
                                         const float* __restrict__ Wk,
                                         const float* __restrict__ Wv,
                                         int row, int lane) {
    const float* W = (row < 1024) ? Wq : (row < 2048) ? Wk : Wv;
    const float4* __restrict__ Wp = (const float4*)(W + (size_t)(row & 1023) * DD);
#pragma unroll
    for (int ii = 0; ii < 8; ii++) dst[ii] = Wp[lane + ii * 32];
}

__device__ __forceinline__ void compute_store(const float4 wr[8],
                                              const float4* __restrict__ xs4,
                                              const float* __restrict__ bq,
                                              const float* __restrict__ bk,
                                              const float* __restrict__ bv,
                                              int row, int lane) {
    float acc[BB];
#pragma unroll
    for (int b = 0; b < BB; b++) acc[b] = 0.f;
#pragma unroll
    for (int ii = 0; ii < 8; ii++) {
        const int i = lane + ii * 32;
#pragma unroll
        for (int b = 0; b < BB; b++) {
            float4 xv = xs4[b * (DD / 4) + i];
            acc[b] += wr[ii].x * xv.x + wr[ii].y * xv.y
                    + wr[ii].z * xv.z + wr[ii].w * xv.w;
        }
    }
#pragma unroll
    for (int off = 16; off > 0; off >>= 1)
#pragma unroll
        for (int b = 0; b < BB; b++)
            acc[b] += __shfl_xor_sync(0xffffffffu, acc[b], off);

    if (lane < BB) {
        const float* bias = (row < 1024) ? bq : (row < 2048) ? bk : bv;
        const int rr = row & 1023;
        const int m  = row >> 10;
        g_qkv[m * BB * DD + lane * DD + rr] = acc[lane] + bias[rr];
    }
}

// ---------------- kernel 1: fused QKV GEMV + RoPE table ----------------
// grid 128 x 256 (single wave). Each warp owns 3 rows of [Wq;Wk;Wv], software-
// pipelined (load row i+1 while computing row i). x staged via cp.async.
__global__ void __launch_bounds__(256) qkv_gemv(
        const float* __restrict__ x,
        const float* __restrict__ Wq, const float* __restrict__ bq,
        const float* __restrict__ Wk, const float* __restrict__ bk,
        const float* __restrict__ Wv, const float* __restrict__ bv) {
    // block 0 also builds the RoPE table (double-precision angles)
    if (blockIdx.x == 0 && threadIdx.x < HD / 2) {
        int i = threadIdx.x;
        double inv = pow(10000.0, -(double)i / (HD / 2));
        double ang = (double)PAST * inv;
        g_cos[i] = (float)cos(ang);
        g_sin[i] = (float)sin(ang);
    }

    __shared__ float xs[BB * DD];

    // x fill via cp.async: no dest registers, issues immediately, overlaps W loads
    {
        uint32_t sbase = (uint32_t)__cvta_generic_to_shared(xs);
        const float4* __restrict__ x4 = (const float4*)x;
#pragma unroll
        for (int i = 0; i < 8; i++)
            cp_async16(sbase + (threadIdx.x + i * 256) * 16, x4 + threadIdx.x + i * 256);
        asm volatile("cp.async.commit_group;");
    }

    const int warp = threadIdx.x >> 5;
    const int lane = threadIdx.x & 31;
    const int rbase = blockIdx.x * 24 + warp;    // rows rbase, rbase+8, rbase+16

    float4 wA[8], wB[8];
    load_row(wA, Wq, Wk, Wv, rbase, lane);       // row 0 loads fly with cp.async

    asm volatile("cp.async.wait_group 0;");
    __syncthreads();

    const float4* __restrict__ xs4 = (const float4*)xs;

    load_row(wB, Wq, Wk, Wv, rbase + 8, lane);   // prefetch row 1
    compute_store(wA, xs4, bq, bk, bv, rbase, lane);
    load_row(wA, Wq, Wk, Wv, rbase + 16, lane);  // prefetch row 2
    compute_store(wB, xs4, bq, bk, bv, rbase + 8, lane);
    compute_store(wA, xs4, bq, bk, bv, rbase + 16, lane);
}

// ---------------- kernel 2: flash-decode + fused final combine ----------------
__global__ void __launch_bounds__(256, 7)
attn_fused(const float* __restrict__ pk, const float* __restrict__ pv) {
    const int split = blockIdx.x, h = blockIdx.y, b = blockIdx.z;
    const int tid = threadIdx.x;
    const int l16 = tid & 15;
    const int hw  = tid >> 4;   // 0..15
    const int bh  = b * HH + h;

    // --- q load + RoPE on the fly ---
    float4 qr = ((const float4*)(g_qkv + b * DD + h * HD))[l16];
    float4 qp;  // partner elements (j +/- 32) live in lane l16^8
    qp.x = __shfl_xor_sync(0xffffffffu, qr.x, 8);
    qp.y = __shfl_xor_sync(0xffffffffu, qr.y, 8);
    qp.z = __shfl_xor_sync(0xffffffffu, qr.z, 8);
    qp.w = __shfl_xor_sync(0xffffffffu, qr.w, 8);
    {
        int j0 = 4 * l16;
        bool lo = (l16 < 8);
        int i0 = lo ? j0 : j0 - 32;
        float sgn = lo ? -1.f : 1.f;
        qr.x = qr.x * g_cos[i0 + 0] + sgn * qp.x * g_sin[i0 + 0];
        qr.y = qr.y * g_cos[i0 + 1] + sgn * qp.y * g_sin[i0 + 1];
        qr.z = qr.z * g_cos[i0 + 2] + sgn * qp.z * g_sin[i0 + 2];
        qr.w = qr.w * g_cos[i0 + 3] + sgn * qp.w * g_sin[i0 + 3];
    }

    const long base = (long)bh * PAST * (HD / 4);
    const float4* __restrict__ K4 = (const float4*)pk + base;
    const float4* __restrict__ V4 = (const float4*)pv + base;

    float l = 0.f;
    float4 acc = make_float4(0.f, 0.f, 0.f, 0.f);

    const int t0 = split * CHUNK;
#pragma unroll 4
    for (int it = 0; it < CHUNK / 16; it++) {
        const int t = t0 + it * 16 + hw;
        float4 kk = __ldcs(K4 + t * 16 + l16);
        float4 vv = __ldcs(V4 + t * 16 + l16);
        float s = kk.x * qr.x + kk.y * qr.y + kk.z * qr.z + kk.w * qr.w;
        s += __shfl_xor_sync(0xffffffffu, s, 8);
        s += __shfl_xor_sync(0xffffffffu, s, 4);
        s += __shfl_xor_sync(0xffffffffu, s, 2);
        s += __shfl_xor_sync(0xffffffffu, s, 1);
        float p = __expf(s * 0.125f);    // 1/sqrt(64); bounded scores, no max needed
        l += p;
        acc.x += p * vv.x;
        acc.y += p * vv.y;
        acc.z += p * vv.z;
        acc.w += p * vv.w;
    }

    // --- block-level combine ---
    __shared__ float sm_l[16];
    __shared__ float sm_o[16][HD];
    if (l16 == 0) sm_l[hw] = l;
    ((float4*)sm_o[hw])[l16] = acc;
    __syncthreads();

    const int pidx = bh * NSPLIT + split;
    if (tid < HD) {
        float num = 0.f;
#pragma unroll
        for (int i = 0; i < 16; i++) num += sm_o[i][tid];
        g_part_o[pidx * HD + tid] = num;
    }
    if (tid == 0) {
        float den = 0.f;
#pragma unroll
        for (int i = 0; i < 16; i++) den += sm_l[i];
        g_part_l[pidx] = den;
    }

    // --- last block for this (b,h) combines everything ---
    __threadfence();
    __syncthreads();
    __shared__ int sflag;
    if (tid == 0) sflag = (atomicAdd(&g_cnt[bh], 1) == NSPLIT - 1);
    __syncthreads();
    if (!sflag) return;
    __threadfence();
    if (tid == 0) g_cnt[bh] = 0;          // reset for next graph replay

    __shared__ float sm_red[2];
    __shared__ float sm_snew;
    if (tid < HD) {
        const float* q = g_qkv + b * DD + h * HD;
        const float* k = g_qkv + BB * DD + b * DD + h * HD;
        float qv, kv;
        if (tid < 32) {
            float c = g_cos[tid], s = g_sin[tid];
            qv = q[tid] * c - q[tid + 32] * s;
            kv = k[tid] * c - k[tid + 32] * s;
        } else {
            float c = g_cos[tid - 32], s = g_sin[tid - 32];
            qv = q[tid] * c + q[tid - 32] * s;
            kv = k[tid] * c + k[tid - 32] * s;
        }
        float prod = qv * kv;
#pragma unroll
        for (int off = 16; off > 0; off >>= 1)
            prod += __shfl_xor_sync(0xffffffffu, prod, off);
        if ((tid & 31) == 0) sm_red[tid >> 5] = prod;
    }
    __syncthreads();
    if (tid == 0) sm_snew = (sm_red[0] + sm_red[1]) * 0.125f;
    __syncthreads();

    if (tid < HD) {
        const float s_new = sm_snew;
        const float wn = __expf(s_new);
        const float* vn = g_qkv + 2 * BB * DD + b * DD + h * HD;
        float num = wn * vn[tid];
        float den = wn;
        const int pb = bh * NSPLIT;
#pragma unroll
        for (int i = 0; i < NSPLIT; i++) {
            num += g_part_o[(pb + i) * HD + tid];
            den += g_part_l[pb + i];
        }
        g_attn[b * DD + h * HD + tid] = num / den;
    }
}

// ---------------- kernel 3: output projection ----------------
// grid 128 x 256, one row per warp; g_attn staged via cp.async.
__global__ void __launch_bounds__(256) out_gemv(
        const float* __restrict__ Wo, const float* __restrict__ bo,
        float* __restrict__ out) {
    __shared__ float xs[BB * DD];
    {
        uint32_t sbase = (uint32_t)__cvta_generic_to_shared(xs);
        const float4* __restrict__ a4 = (const float4*)g_attn;
#pragma unroll
        for (int i = 0; i < 8; i++)
            cp_async16(sbase + (threadIdx.x + i * 256) * 16, a4 + threadIdx.x + i * 256);
        asm volatile("cp.async.commit_group;");
    }

    const int warp = threadIdx.x >> 5;
    const int lane = threadIdx.x & 31;
    const int r = blockIdx.x * 8 + warp;

    const float4* __restrict__ W4 = (const float4*)(Wo + (size_t)r * DD);
    float4 wr[8];
#pragma unroll
    for (int ii = 0; ii < 8; ii++) wr[ii] = W4[lane + ii * 32];

    asm volatile("cp.async.wait_group 0;");
    __syncthreads();

    float acc[BB];
#pragma unroll
    for (int b = 0; b < BB; b++) acc[b] = 0.f;

    const float4* __restrict__ xs4 = (const float4*)xs;
#pragma unroll
    for (int ii = 0; ii < 8; ii++) {
        const int i = lane + ii * 32;
#pragma unroll
        for (int b = 0; b < BB; b++) {
            float4 xv = xs4[b * (DD / 4) + i];
            acc[b] += wr[ii].x * xv.x + wr[ii].y * xv.y + wr[ii].z * xv.z + wr[ii].w * xv.w;
        }
    }
#pragma unroll
    for (int off = 16; off > 0; off >>= 1)
#pragma unroll
        for (int b = 0; b < BB; b++)
            acc[b] += __shfl_xor_sync(0xffffffffu, acc[b], off);

    if (lane < BB)
        out[lane * DD + r] = acc[lane] + bo[r];
}

// ---------------- launcher ----------------
extern "C" void kernel_launch(void* const* d_in, const int* in_sizes, int n_in,
                              void* d_out, int out_size) {
    const float* x      = (const float*)d_in[0];
    const float* Wq     = (const float*)d_in[1];
    const float* bq     = (const float*)d_in[2];
    const float* Wk     = (const float*)d_in[3];
    const float* bk     = (const float*)d_in[4];
    const float* Wv     = (const float*)d_in[5];
    const float* bv     = (const float*)d_in[6];
    const float* Wo     = (const float*)d_in[7];
    const float* bo     = (const float*)d_in[8];
    const float* past_k = (const float*)d_in[9];
    const float* past_v = (const float*)d_in[10];
    float* out = (float*)d_out;

    qkv_gemv<<<128, 256>>>(x, Wq, bq, Wk, bk, Wv, bv);
    attn_fused<<<dim3(NSPLIT, HH, BB), 256>>>(past_k, past_v);
    out_gemv<<<DD / 8, 256>>>(Wo, bo, out);
}

// round 7
// speedup vs baseline: 1.0305x; 1.0305x over previous
#include <cuda_runtime.h>
#include <math.h>

#define BB 8
#define DD 1024
#define HH 16
#define HD 64
#define PAST 8192
#define NSPLIT 8
#define CHUNK (PAST / NSPLIT)   // 1024 keys per block

// ---------------- scratch (no allocations allowed) ----------------
__device__ float g_qkv[3 * BB * DD];               // [m][b][d] raw (pre-RoPE) q,k,v
__device__ float g_part_o[BB * HH * NSPLIT * HD];  // sum p*v per split
__device__ float g_part_l[BB * HH * NSPLIT];       // sum p per split
__device__ float g_attn[BB * DD];                  // attention output before Wo
__device__ float g_cos[HD / 2];
__device__ float g_sin[HD / 2];
__device__ int   g_cnt[BB * HH];                   // zero-init; self-resetting

// ---------------- kernel 1: fused QKV GEMV + RoPE table ----------------
// One output row per BLOCK (3072 blocks x 256 threads). Each thread loads ONE
// float4 of the weight row (fully parallel across 64 warps/SM -> bandwidth-
// bound) and 8 float4 of x (L1-resident after first block per SM).
__global__ void __launch_bounds__(256) qkv_gemv(
        const float* __restrict__ x,
        const float* __restrict__ Wq, const float* __restrict__ bq,
        const float* __restrict__ Wk, const float* __restrict__ bk,
        const float* __restrict__ Wv, const float* __restrict__ bv) {
    const int row_g = blockIdx.x;        // 0..3071
    const int m = row_g >> 10;
    const int r = row_g & 1023;
    const int t = threadIdx.x;           // 0..255, covers columns 4t..4t+3
    const int warp = t >> 5;
    const int lane = t & 31;

    // block 0 also builds the RoPE table (double-precision angles)
    if (row_g == 0 && t >= 224) {        // last warp: no extra divergence on warp 0
        int i = t - 224;                 // 0..31
        double inv = pow(10000.0, -(double)i / (HD / 2));
        double ang = (double)PAST * inv;
        g_cos[i] = (float)cos(ang);
        g_sin[i] = (float)sin(ang);
    }

    const float* W    = (m == 0) ? Wq : (m == 1) ? Wk : Wv;
    const float* bias = (m == 0) ? bq : (m == 1) ? bk : bv;

    const float4 w = ((const float4*)(W + (size_t)r * DD))[t];
    const float4* __restrict__ x4 = (const float4*)x;

    float acc[BB];
#pragma unroll
    for (int b = 0; b < BB; b++) {
        float4 xv = __ldg(x4 + b * (DD / 4) + t);
        acc[b] = w.x * xv.x + w.y * xv.y + w.z * xv.z + w.w * xv.w;
    }

    // intra-warp reduce (8 accumulators)
#pragma unroll
    for (int off = 16; off > 0; off >>= 1)
#pragma unroll
        for (int b = 0; b < BB; b++)
            acc[b] += __shfl_xor_sync(0xffffffffu, acc[b], off);

    __shared__ float sm[8][BB];          // [warp][batch]
    if (lane == 0) {
#pragma unroll
        for (int b = 0; b < BB; b++) sm[warp][b] = acc[b];
    }
    __syncthreads();

    if (t < BB) {                        // t = batch index
        float s = 0.f;
#pragma unroll
        for (int wi = 0; wi < 8; wi++) s += sm[wi][t];
        g_qkv[m * BB * DD + t * DD + r] = s + bias[r];
    }
}

// ---------------- kernel 2: flash-decode + fused final combine ----------------
__global__ void __launch_bounds__(256, 7)
attn_fused(const float* __restrict__ pk, const float* __restrict__ pv) {
    const int split = blockIdx.x, h = blockIdx.y, b = blockIdx.z;
    const int tid = threadIdx.x;
    const int l16 = tid & 15;
    const int hw  = tid >> 4;   // 0..15
    const int bh  = b * HH + h;

    // --- q load + RoPE on the fly ---
    float4 qr = ((const float4*)(g_qkv + b * DD + h * HD))[l16];
    float4 qp;  // partner elements (j +/- 32) live in lane l16^8
    qp.x = __shfl_xor_sync(0xffffffffu, qr.x, 8);
    qp.y = __shfl_xor_sync(0xffffffffu, qr.y, 8);
    qp.z = __shfl_xor_sync(0xffffffffu, qr.z, 8);
    qp.w = __shfl_xor_sync(0xffffffffu, qr.w, 8);
    {
        int j0 = 4 * l16;
        bool lo = (l16 < 8);
        int i0 = lo ? j0 : j0 - 32;
        float sgn = lo ? -1.f : 1.f;
        qr.x = qr.x * g_cos[i0 + 0] + sgn * qp.x * g_sin[i0 + 0];
        qr.y = qr.y * g_cos[i0 + 1] + sgn * qp.y * g_sin[i0 + 1];
        qr.z = qr.z * g_cos[i0 + 2] + sgn * qp.z * g_sin[i0 + 2];
        qr.w = qr.w * g_cos[i0 + 3] + sgn * qp.w * g_sin[i0 + 3];
    }

    const long base = (long)bh * PAST * (HD / 4);
    const float4* __restrict__ K4 = (const float4*)pk + base;
    const float4* __restrict__ V4 = (const float4*)pv + base;

    float l = 0.f;
    float4 acc = make_float4(0.f, 0.f, 0.f, 0.f);

    const int t0 = split * CHUNK;
#pragma unroll 4
    for (int it = 0; it < CHUNK / 16; it++) {
        const int t = t0 + it * 16 + hw;
        float4 kk = __ldcs(K4 + t * 16 + l16);
        float4 vv = __ldcs(V4 + t * 16 + l16);
        float s = kk.x * qr.x + kk.y * qr.y + kk.z * qr.z + kk.w * qr.w;
        s += __shfl_xor_sync(0xffffffffu, s, 8);
        s += __shfl_xor_sync(0xffffffffu, s, 4);
        s += __shfl_xor_sync(0xffffffffu, s, 2);
        s += __shfl_xor_sync(0xffffffffu, s, 1);
        float p = __expf(s * 0.125f);    // 1/sqrt(64); bounded scores, no max needed
        l += p;
        acc.x += p * vv.x;
        acc.y += p * vv.y;
        acc.z += p * vv.z;
        acc.w += p * vv.w;
    }

    // --- block-level combine ---
    __shared__ float sm_l[16];
    __shared__ float sm_o[16][HD];
    if (l16 == 0) sm_l[hw] = l;
    ((float4*)sm_o[hw])[l16] = acc;
    __syncthreads();

    const int pidx = bh * NSPLIT + split;
    if (tid < HD) {
        float num = 0.f;
#pragma unroll
        for (int i = 0; i < 16; i++) num += sm_o[i][tid];
        g_part_o[pidx * HD + tid] = num;
    }
    if (tid == 0) {
        float den = 0.f;
#pragma unroll
        for (int i = 0; i < 16; i++) den += sm_l[i];
        g_part_l[pidx] = den;
    }

    // --- last block for this (b,h) combines everything ---
    __threadfence();
    __syncthreads();
    __shared__ int sflag;
    if (tid == 0) sflag = (atomicAdd(&g_cnt[bh], 1) == NSPLIT - 1);
    __syncthreads();
    if (!sflag) return;
    __threadfence();
    if (tid == 0) g_cnt[bh] = 0;          // reset for next graph replay

    __shared__ float sm_red[2];
    __shared__ float sm_snew;
    if (tid < HD) {
        const float* q = g_qkv + b * DD + h * HD;
        const float* k = g_qkv + BB * DD + b * DD + h * HD;
        float qv, kv;
        if (tid < 32) {
            float c = g_cos[tid], s = g_sin[tid];
            qv = q[tid] * c - q[tid + 32] * s;
            kv = k[tid] * c - k[tid + 32] * s;
        } else {
            float c = g_cos[tid - 32], s = g_sin[tid - 32];
            qv = q[tid] * c + q[tid - 32] * s;
            kv = k[tid] * c + k[tid - 32] * s;
        }
        float prod = qv * kv;
#pragma unroll
        for (int off = 16; off > 0; off >>= 1)
            prod += __shfl_xor_sync(0xffffffffu, prod, off);
        if ((tid & 31) == 0) sm_red[tid >> 5] = prod;
    }
    __syncthreads();
    if (tid == 0) sm_snew = (sm_red[0] + sm_red[1]) * 0.125f;
    __syncthreads();

    if (tid < HD) {
        const float s_new = sm_snew;
        const float wn = __expf(s_new);
        const float* vn = g_qkv + 2 * BB * DD + b * DD + h * HD;
        float num = wn * vn[tid];
        float den = wn;
        const int pb = bh * NSPLIT;
#pragma unroll
        for (int i = 0; i < NSPLIT; i++) {
            num += g_part_o[(pb + i) * HD + tid];
            den += g_part_l[pb + i];
        }
        g_attn[b * DD + h * HD + tid] = num / den;
    }
}

// ---------------- kernel 3: output projection ----------------
// Same one-row-per-block structure: 1024 blocks x 256 threads.
__global__ void __launch_bounds__(256) out_gemv(
        const float* __restrict__ Wo, const float* __restrict__ bo,
        float* __restrict__ out) {
    const int r = blockIdx.x;            // 0..1023
    const int t = threadIdx.x;
    const int warp = t >> 5;
    const int lane = t & 31;

    const float4 w = ((const float4*)(Wo + (size_t)r * DD))[t];
    const float4* __restrict__ a4 = (const float4*)g_attn;

    float acc[BB];
#pragma unroll
    for (int b = 0; b < BB; b++) {
        float4 xv = __ldg(a4 + b * (DD / 4) + t);
        acc[b] = w.x * xv.x + w.y * xv.y + w.z * xv.z + w.w * xv.w;
    }

#pragma unroll
    for (int off = 16; off > 0; off >>= 1)
#pragma unroll
        for (int b = 0; b < BB; b++)
            acc[b] += __shfl_xor_sync(0xffffffffu, acc[b], off);

    __shared__ float sm[8][BB];
    if (lane == 0) {
#pragma unroll
        for (int b = 0; b < BB; b++) sm[warp][b] = acc[b];
    }
    __syncthreads();

    if (t < BB) {
        float s = 0.f;
#pragma unroll
        for (int wi = 0; wi < 8; wi++) s += sm[wi][t];
        out[t * DD + r] = s + bo[r];
    }
}

// ---------------- launcher ----------------
extern "C" void kernel_launch(void* const* d_in, const int* in_sizes, int n_in,
                              void* d_out, int out_size) {
    const float* x      = (const float*)d_in[0];
    const float* Wq     = (const float*)d_in[1];
    const float* bq     = (const float*)d_in[2];
    const float* Wk     = (const float*)d_in[3];
    const float* bk     = (const float*)d_in[4];
    const float* Wv     = (const float*)d_in[5];
    const float* bv     = (const float*)d_in[6];
    const float* Wo     = (const float*)d_in[7];
    const float* bo     = (const float*)d_in[8];
    const float* past_k = (const float*)d_in[9];
    const float* past_v = (const float*)d_in[10];
    float* out = (float*)d_out;

    qkv_gemv<<<3 * DD, 256>>>(x, Wq, bq, Wk, bk, Wv, bv);
    attn_fused<<<dim3(NSPLIT, HH, BB), 256>>>(past_k, past_v);
    out_gemv<<<DD, 256>>>(Wo, bo, out);
}